// round 1
// baseline (speedup 1.0000x reference)
#include <cuda_runtime.h>

#define BATCH 64
#define LSEQ 500
#define FEAT 256
#define HEADS 4
#define DK 64
#define MROWS (BATCH*LSEQ)           // 32000

// scratch (no allocs allowed -> device globals)
static __device__ float g_qh[BATCH*HEADS*LSEQ*DK];   // [B,H,L,dk]
static __device__ float g_vh[BATCH*HEADS*LSEQ*DK];   // [B,H,L,dk]
static __device__ float g_pre[MROWS*FEAT];           // [B,L,F] pre-fc

// ---------------------------------------------------------------------------
// Kernel 1: projection  X[32000,256] @ W[256,256] -> head-major [B,H,L,dk]
// grid (500, 4), block 256. which: 0 -> g_qh, 1 -> g_vh
// ---------------------------------------------------------------------------
__global__ __launch_bounds__(256) void proj_kernel(
    const float* __restrict__ X, const float* __restrict__ W, int which)
{
    __shared__ float As[16][65];   // [k][m] transposed, padded
    __shared__ float Bs[16][64];   // [k][n]

    float* __restrict__ O = which ? g_vh : g_qh;

    const int tid = threadIdx.x;
    const int tx = tid & 15, ty = tid >> 4;
    const int m0 = blockIdx.x * 64;
    const int h  = blockIdx.y;          // N tile == head (dk = 64)
    const int n0 = h * 64;

    float acc[4][4];
#pragma unroll
    for (int i = 0; i < 4; i++)
#pragma unroll
        for (int j = 0; j < 4; j++) acc[i][j] = 0.f;

    const int la_m = tid >> 2;          // 0..63
    const int la_k = (tid & 3) * 4;     // 0,4,8,12
    const int lb_k = tid >> 4;          // 0..15
    const int lb_n = (tid & 15) * 4;    // 0..60

    for (int k0 = 0; k0 < FEAT; k0 += 16) {
        float4 av = *reinterpret_cast<const float4*>(&X[(m0 + la_m) * FEAT + k0 + la_k]);
        float4 bv = *reinterpret_cast<const float4*>(&W[(k0 + lb_k) * FEAT + n0 + lb_n]);
        __syncthreads();
        As[la_k + 0][la_m] = av.x;
        As[la_k + 1][la_m] = av.y;
        As[la_k + 2][la_m] = av.z;
        As[la_k + 3][la_m] = av.w;
        *reinterpret_cast<float4*>(&Bs[lb_k][lb_n]) = bv;
        __syncthreads();
#pragma unroll
        for (int k = 0; k < 16; k++) {
            float a[4];
#pragma unroll
            for (int i = 0; i < 4; i++) a[i] = As[k][ty * 4 + i];
            float4 b4 = *reinterpret_cast<const float4*>(&Bs[k][tx * 4]);
#pragma unroll
            for (int i = 0; i < 4; i++) {
                acc[i][0] += a[i] * b4.x;
                acc[i][1] += a[i] * b4.y;
                acc[i][2] += a[i] * b4.z;
                acc[i][3] += a[i] * b4.w;
            }
        }
    }
    // epilogue: [m, h*64+d] -> qh[((b*H+h)*L + l)*dk + d]
#pragma unroll
    for (int i = 0; i < 4; i++) {
        int m = m0 + ty * 4 + i;
        int b = m / LSEQ;
        int l = m - b * LSEQ;
        float4 v = make_float4(acc[i][0], acc[i][1], acc[i][2], acc[i][3]);
        *reinterpret_cast<float4*>(&O[((b * HEADS + h) * LSEQ + l) * DK + tx * 4]) = v;
    }
}

// ---------------------------------------------------------------------------
// Kernel 2: dense synthesizer + softmax + attn@vh.
// grid (8, 256): x = 64-row tile of L, y = b*H + h. block 256.
// dyn smem: logits[64*500] | qs[64*65] | hid[64*65] | chunk[64*64] | b1s[64] | rinv[64]
// ---------------------------------------------------------------------------
#define SYN_SMEM_FLOATS (64*500 + 64*65 + 64*65 + 64*64 + 64 + 64)

__global__ __launch_bounds__(256) void synth_kernel(
    const float* __restrict__ w1, const float* __restrict__ b1,
    const float* __restrict__ w2, const float* __restrict__ b2)
{
    extern __shared__ float sm[];
    float* logits = sm;                       // [64][500]
    float* qs     = sm + 64 * 500;            // [64][65]
    float* hid    = qs + 64 * 65;             // [64][65]
    float* chunk  = hid + 64 * 65;            // [64][64]  (w1 / w2-chunk / vh-chunk)
    float* b1s    = chunk + 64 * 64;          // [64]
    float* rinv   = b1s + 64;                 // [64]

    const int tid = threadIdx.x;
    const int tx = tid & 15, ty = tid >> 4;
    const int bh = blockIdx.y;
    const int row0 = blockIdx.x * 64;
    const int nrows = min(64, LSEQ - row0);

    // load qh tile (zero-fill padded rows) + w1 + b1
    {
        const float* src = &g_qh[(bh * LSEQ + row0) * DK];
        for (int i = tid; i < 64 * DK; i += 256) {
            int r = i >> 6, d = i & 63;
            qs[r * 65 + d] = (r < nrows) ? src[r * DK + d] : 0.f;
        }
        for (int i = tid; i < DK * DK; i += 256) chunk[i] = w1[i];
        if (tid < 64) b1s[tid] = b1[tid];
    }
    __syncthreads();

    // phase 1: hid = relu(qs @ w1 + b1)
    {
        float acc[4][4];
#pragma unroll
        for (int j = 0; j < 4; j++) {
            float bb = b1s[tx * 4 + j];
#pragma unroll
            for (int i = 0; i < 4; i++) acc[i][j] = bb;
        }
#pragma unroll 8
        for (int d = 0; d < DK; d++) {
            float a[4];
#pragma unroll
            for (int i = 0; i < 4; i++) a[i] = qs[(ty * 4 + i) * 65 + d];
            float4 w4 = *reinterpret_cast<const float4*>(&chunk[d * 64 + tx * 4]);
#pragma unroll
            for (int i = 0; i < 4; i++) {
                acc[i][0] += a[i] * w4.x;
                acc[i][1] += a[i] * w4.y;
                acc[i][2] += a[i] * w4.z;
                acc[i][3] += a[i] * w4.w;
            }
        }
#pragma unroll
        for (int i = 0; i < 4; i++)
#pragma unroll
            for (int j = 0; j < 4; j++)
                hid[(ty * 4 + i) * 65 + tx * 4 + j] = fmaxf(acc[i][j], 0.f);
    }
    __syncthreads();

    // phase 2: logits = hid @ w2 + b2 (8 column passes of 64)
    for (int cp = 0; cp < 8; cp++) {
        const int cbase = cp * 64;
        const int cw = min(64, LSEQ - cbase);
        __syncthreads();
        for (int i = tid; i < 64 * 64; i += 256) {
            int j = i >> 6, cc = i & 63;
            chunk[i] = (cc < cw) ? w2[j * LSEQ + cbase + cc] : 0.f;
        }
        __syncthreads();
        float acc[4][4];
#pragma unroll
        for (int j = 0; j < 4; j++) {
            int c = cbase + tx * 4 + j;
            float bb = (c < LSEQ) ? __ldg(&b2[c]) : 0.f;
#pragma unroll
            for (int i = 0; i < 4; i++) acc[i][j] = bb;
        }
#pragma unroll 8
        for (int jj = 0; jj < DK; jj++) {
            float a[4];
#pragma unroll
            for (int i = 0; i < 4; i++) a[i] = hid[(ty * 4 + i) * 65 + jj];
            float4 w4 = *reinterpret_cast<const float4*>(&chunk[jj * 64 + tx * 4]);
#pragma unroll
            for (int i = 0; i < 4; i++) {
                acc[i][0] += a[i] * w4.x;
                acc[i][1] += a[i] * w4.y;
                acc[i][2] += a[i] * w4.z;
                acc[i][3] += a[i] * w4.w;
            }
        }
#pragma unroll
        for (int i = 0; i < 4; i++)
#pragma unroll
            for (int j = 0; j < 4; j++) {
                int c = cbase + tx * 4 + j;
                if (c < LSEQ) logits[(ty * 4 + i) * LSEQ + c] = acc[i][j];
            }
    }
    __syncthreads();

    // softmax per row (unnormalized probs; 1/sum folded into epilogue)
    {
        const int warp = tid >> 5, lane = tid & 31;
        for (int rr = 0; rr < 8; rr++) {
            int r = warp * 8 + rr;
            if (r >= nrows) break;
            float* row = &logits[r * LSEQ];
            float m = -1e30f;
            for (int c = lane; c < LSEQ; c += 32) m = fmaxf(m, row[c]);
#pragma unroll
            for (int o = 16; o; o >>= 1) m = fmaxf(m, __shfl_xor_sync(0xffffffffu, m, o));
            float s = 0.f;
            for (int c = lane; c < LSEQ; c += 32) {
                float p = __expf(row[c] - m);
                row[c] = p;
                s += p;
            }
#pragma unroll
            for (int o = 16; o; o >>= 1) s += __shfl_xor_sync(0xffffffffu, s, o);
            if (lane == 0) rinv[r] = 1.f / s;
        }
    }
    __syncthreads();

    // phase 3: out = probs @ vh  (8 k-passes of 64; padded vh rows zero-filled)
    float acc[4][4];
#pragma unroll
    for (int i = 0; i < 4; i++)
#pragma unroll
        for (int j = 0; j < 4; j++) acc[i][j] = 0.f;

    for (int cp = 0; cp < 8; cp++) {
        const int cbase = cp * 64;
        const int cw = min(64, LSEQ - cbase);
        __syncthreads();
        for (int i = tid; i < 64 * 64; i += 256) {
            int cc = i >> 6, d = i & 63;
            chunk[i] = (cc < cw) ? g_vh[(bh * LSEQ + cbase + cc) * DK + d] : 0.f;
        }
        __syncthreads();
#pragma unroll 8
        for (int cc = 0; cc < 64; cc++) {             // zero-fill makes tail safe
            int c = cbase + cc;
            float p[4];
#pragma unroll
            for (int i = 0; i < 4; i++) p[i] = logits[(ty * 4 + i) * LSEQ + c];
            float4 v4 = *reinterpret_cast<const float4*>(&chunk[cc * 64 + tx * 4]);
#pragma unroll
            for (int i = 0; i < 4; i++) {
                acc[i][0] += p[i] * v4.x;
                acc[i][1] += p[i] * v4.y;
                acc[i][2] += p[i] * v4.z;
                acc[i][3] += p[i] * v4.w;
            }
        }
    }
    // epilogue: scale by 1/sum, write [B,L,F]
    const int b = bh >> 2, h = bh & 3;
#pragma unroll
    for (int i = 0; i < 4; i++) {
        int r = ty * 4 + i;
        if (r < nrows) {
            float sc = rinv[r];
            float4 o = make_float4(acc[i][0] * sc, acc[i][1] * sc, acc[i][2] * sc, acc[i][3] * sc);
            *reinterpret_cast<float4*>(
                &g_pre[(b * LSEQ + row0 + r) * FEAT + h * 64 + tx * 4]) = o;
        }
    }
}

// ---------------------------------------------------------------------------
// Kernel 3: out = LayerNorm(pre @ fc_w + q). grid 2000, block 256, 16 rows/CTA.
// ---------------------------------------------------------------------------
#define RT 16
__global__ __launch_bounds__(256) void fc_ln_kernel(
    const float* __restrict__ q, const float* __restrict__ fcw,
    const float* __restrict__ g, const float* __restrict__ bta,
    float* __restrict__ out)
{
    __shared__ float xs[RT][FEAT];
    __shared__ float mu_s[RT], rs_s[RT];

    const int tid = threadIdx.x;
    const int m0 = blockIdx.x * RT;

    for (int i = tid; i < RT * FEAT; i += 256) {
        int r = i >> 8, c = i & 255;
        xs[r][c] = g_pre[(m0 + r) * FEAT + c];
    }
    __syncthreads();

    float acc[RT];
#pragma unroll
    for (int r = 0; r < RT; r++) acc[r] = 0.f;

#pragma unroll 4
    for (int k = 0; k < FEAT; k++) {
        float w = fcw[k * FEAT + tid];
#pragma unroll
        for (int r = 0; r < RT; r++) acc[r] += xs[r][k] * w;
    }
#pragma unroll
    for (int r = 0; r < RT; r++) acc[r] += q[(m0 + r) * FEAT + tid];

    __syncthreads();
#pragma unroll
    for (int r = 0; r < RT; r++) xs[r][tid] = acc[r];
    __syncthreads();

    {
        const int warp = tid >> 5, lane = tid & 31;
#pragma unroll
        for (int rr = 0; rr < 2; rr++) {
            int r = warp * 2 + rr;
            float s = 0.f, s2 = 0.f;
#pragma unroll
            for (int i = 0; i < 8; i++) {
                float v = xs[r][lane + i * 32];
                s += v; s2 += v * v;
            }
#pragma unroll
            for (int o = 16; o; o >>= 1) {
                s  += __shfl_xor_sync(0xffffffffu, s, o);
                s2 += __shfl_xor_sync(0xffffffffu, s2, o);
            }
            if (lane == 0) {
                float mu = s * (1.f / FEAT);
                mu_s[r] = mu;
                rs_s[r] = rsqrtf(s2 * (1.f / FEAT) - mu * mu + 1e-6f);
            }
        }
    }
    __syncthreads();

    float gn = g[tid], bn = bta[tid];
#pragma unroll
    for (int r = 0; r < RT; r++) {
        out[(m0 + r) * FEAT + tid] = (acc[r] - mu_s[r]) * rs_s[r] * gn + bn;
    }
}

// ---------------------------------------------------------------------------
extern "C" void kernel_launch(void* const* d_in, const int* in_sizes, int n_in,
                              void* d_out, int out_size)
{
    (void)in_sizes; (void)n_in; (void)out_size;
    const float* q    = (const float*)d_in[0];
    // d_in[1] = k (unused by the reference math)
    const float* v    = (const float*)d_in[2];
    const float* w_qs = (const float*)d_in[3];
    const float* w_vs = (const float*)d_in[4];
    const float* w1   = (const float*)d_in[5];
    const float* b1   = (const float*)d_in[6];
    const float* w2   = (const float*)d_in[7];
    const float* b2   = (const float*)d_in[8];
    const float* fcw  = (const float*)d_in[9];
    const float* lng  = (const float*)d_in[10];
    const float* lnb  = (const float*)d_in[11];
    float* out = (float*)d_out;

    const int syn_smem = SYN_SMEM_FLOATS * (int)sizeof(float);   // 178,176 B
    cudaFuncSetAttribute(synth_kernel,
                         cudaFuncAttributeMaxDynamicSharedMemorySize, syn_smem);

    proj_kernel<<<dim3(500, 4), 256>>>(q, w_qs, 0);
    proj_kernel<<<dim3(500, 4), 256>>>(v, w_vs, 1);
    synth_kernel<<<dim3(8, BATCH * HEADS), 256, syn_smem>>>(w1, b1, w2, b2);
    fc_ln_kernel<<<dim3(MROWS / RT), 256>>>(q, fcw, lng, lnb, out);
}

// round 6
// speedup vs baseline: 3.1925x; 3.1925x over previous
#include <cuda_runtime.h>
#include <cuda_bf16.h>
#include <cstdint>

#define BATCH 64
#define LSEQ  500
#define FEAT  256
#define HEADS 4
#define DK    64
#define BH    (BATCH*HEADS)       // 256
#define MROWS (BATCH*LSEQ)        // 32000
#define LPAD  512
#define AST   72                  // smem row stride (bf16 elems) -> 144B, conflict-free

// ---------------- device scratch (no allocs allowed) ----------------
static __device__ __nv_bfloat16 g_q_hi[MROWS*FEAT],  g_q_lo[MROWS*FEAT];
static __device__ __nv_bfloat16 g_v_hi[MROWS*FEAT],  g_v_lo[MROWS*FEAT];
static __device__ __nv_bfloat16 g_wqsT_hi[FEAT*FEAT], g_wqsT_lo[FEAT*FEAT];
static __device__ __nv_bfloat16 g_wvsT_hi[FEAT*FEAT], g_wvsT_lo[FEAT*FEAT];
static __device__ __nv_bfloat16 g_fcwT_hi[FEAT*FEAT], g_fcwT_lo[FEAT*FEAT];
static __device__ __nv_bfloat16 g_w1t_hi[DK*DK],      g_w1t_lo[DK*DK];
static __device__ __nv_bfloat16 g_w2t_hi[LPAD*DK],    g_w2t_lo[LPAD*DK];
static __device__ float         g_b2p[LPAD];
static __device__ __nv_bfloat16 g_qh_hi[BH*LSEQ*DK],  g_qh_lo[BH*LSEQ*DK];   // [bh][l][d]
static __device__ __nv_bfloat16 g_vT_hi[BH*DK*LPAD],  g_vT_lo[BH*DK*LPAD];   // [bh][d][l] pad 0
static __device__ __nv_bfloat16 g_pre_hi[MROWS*FEAT], g_pre_lo[MROWS*FEAT];  // [m][256]

// ---------------- helpers ----------------
__device__ __forceinline__ uint32_t pack2(__nv_bfloat16 a, __nv_bfloat16 b) {
    return (uint32_t)__bfloat16_as_ushort(a) | ((uint32_t)__bfloat16_as_ushort(b) << 16);
}
__device__ __forceinline__ void split1(float x, __nv_bfloat16& h, __nv_bfloat16& l) {
    h = __float2bfloat16(x);
    l = __float2bfloat16(x - __bfloat162float(h));
}
__device__ __forceinline__ void split2(float x0, float x1, uint32_t& hi, uint32_t& lo) {
    __nv_bfloat16 h0, l0, h1, l1;
    split1(x0, h0, l0);
    split1(x1, h1, l1);
    hi = pack2(h0, h1);
    lo = pack2(l0, l1);
}

__device__ __forceinline__ void mma_bf16(float acc[4], uint32_t a0, uint32_t a1,
                                         uint32_t a2, uint32_t a3,
                                         uint32_t b0, uint32_t b1) {
    asm volatile(
        "mma.sync.aligned.m16n8k16.row.col.f32.bf16.bf16.f32 "
        "{%0,%1,%2,%3}, {%4,%5,%6,%7}, {%8,%9}, {%0,%1,%2,%3};"
        : "+f"(acc[0]), "+f"(acc[1]), "+f"(acc[2]), "+f"(acc[3])
        : "r"(a0), "r"(a1), "r"(a2), "r"(a3), "r"(b0), "r"(b1));
}

// one 64-deep K chunk: A tile [128][64] (rows mw..mw+15 for this warp),
// B tile [NF*8][64], both stride AST, split hi/lo; 3-term product.
template <int NF>
__device__ __forceinline__ void mma_chunk(float (*acc)[4],
                                          const char* aH, const char* aL,
                                          const char* bH, const char* bL,
                                          int mw, int g, int tg) {
#pragma unroll
    for (int ks = 0; ks < 4; ks++) {
        unsigned a0off = (unsigned)(((mw + g) * AST + ks * 16 + tg * 2) * 2);
        unsigned a1off = a0off + 8 * AST * 2;
        uint32_t ah0 = *(const uint32_t*)(aH + a0off);
        uint32_t ah1 = *(const uint32_t*)(aH + a1off);
        uint32_t ah2 = *(const uint32_t*)(aH + a0off + 16);
        uint32_t ah3 = *(const uint32_t*)(aH + a1off + 16);
        uint32_t al0 = *(const uint32_t*)(aL + a0off);
        uint32_t al1 = *(const uint32_t*)(aL + a1off);
        uint32_t al2 = *(const uint32_t*)(aL + a0off + 16);
        uint32_t al3 = *(const uint32_t*)(aL + a1off + 16);
#pragma unroll
        for (int j = 0; j < NF; j++) {
            unsigned boff = (unsigned)(((j * 8 + g) * AST + ks * 16 + tg * 2) * 2);
            uint32_t bh0 = *(const uint32_t*)(bH + boff);
            uint32_t bh1 = *(const uint32_t*)(bH + boff + 16);
            uint32_t bl0 = *(const uint32_t*)(bL + boff);
            uint32_t bl1 = *(const uint32_t*)(bL + boff + 16);
            mma_bf16(acc[j], ah0, ah1, ah2, ah3, bh0, bh1);
            mma_bf16(acc[j], ah0, ah1, ah2, ah3, bl0, bl1);
            mma_bf16(acc[j], al0, al1, al2, al3, bh0, bh1);
        }
    }
}

// copy rows x 128B from gmem (stride gstride bytes) into stride-144B smem, zero-fill
__device__ __forceinline__ void cp_tile(char* dst, const char* src, int rows,
                                        int valid, int gstride, int tid) {
    for (int i = tid; i < rows * 8; i += 256) {
        int r = i >> 3, c = (i & 7) << 4;
        uint4 v = make_uint4(0u, 0u, 0u, 0u);
        if (r < valid) v = *(const uint4*)(src + (size_t)r * gstride + c);
        *(uint4*)(dst + r * (AST * 2) + c) = v;
    }
}

// ---------------------------------------------------------------------------
// convert q, v to split bf16
// ---------------------------------------------------------------------------
__global__ __launch_bounds__(256) void convert_kernel(const float* __restrict__ q,
                                                      const float* __restrict__ v) {
    int i0 = blockIdx.x * blockDim.x + threadIdx.x;
    int nt = gridDim.x * blockDim.x;
    for (int t = i0; t < MROWS * FEAT / 4; t += nt) {
        int e = t * 4;
        float4 a = *(const float4*)(q + e);
        uint32_t h0, l0, h1, l1;
        split2(a.x, a.y, h0, l0);
        split2(a.z, a.w, h1, l1);
        *(uint2*)(g_q_hi + e) = make_uint2(h0, h1);
        *(uint2*)(g_q_lo + e) = make_uint2(l0, l1);
        a = *(const float4*)(v + e);
        split2(a.x, a.y, h0, l0);
        split2(a.z, a.w, h1, l1);
        *(uint2*)(g_v_hi + e) = make_uint2(h0, h1);
        *(uint2*)(g_v_lo + e) = make_uint2(l0, l1);
    }
}

// ---------------------------------------------------------------------------
// weight setup: transpose + split
// ---------------------------------------------------------------------------
__global__ __launch_bounds__(256) void setup_w(const float* __restrict__ w_qs,
                                               const float* __restrict__ w_vs,
                                               const float* __restrict__ fcw,
                                               const float* __restrict__ w1,
                                               const float* __restrict__ w2,
                                               const float* __restrict__ b2) {
    int i0 = blockIdx.x * blockDim.x + threadIdx.x;
    int nt = gridDim.x * blockDim.x;
    for (int t = i0; t < FEAT * FEAT; t += nt) {
        int n = t >> 8, k = t & 255;
        split1(w_qs[k * FEAT + n], g_wqsT_hi[t], g_wqsT_lo[t]);
        split1(w_vs[k * FEAT + n], g_wvsT_hi[t], g_wvsT_lo[t]);
        split1(fcw [k * FEAT + n], g_fcwT_hi[t], g_fcwT_lo[t]);
    }
    for (int t = i0; t < DK * DK; t += nt) {
        int n = t >> 6, k = t & 63;
        split1(w1[k * DK + n], g_w1t_hi[t], g_w1t_lo[t]);
    }
    for (int t = i0; t < LPAD * DK; t += nt) {
        int n = t >> 6, k = t & 63;
        float f = (n < LSEQ) ? w2[k * LSEQ + n] : 0.f;
        split1(f, g_w2t_hi[t], g_w2t_lo[t]);
    }
    for (int t = i0; t < LPAD; t += nt)
        g_b2p[t] = (t < LSEQ) ? b2[t] : -1e30f;
}

// ---------------------------------------------------------------------------
// proj: X[32000,256] @ W -> qh [bh][l][d]  /  vT [bh][d][l]
// grid (BATCH*4, HEADS, 2), block 256 (8 warps, 16 rows each)
// ---------------------------------------------------------------------------
#define PROJ_SMEM (18432*2 + 9216*2)

__global__ __launch_bounds__(256) void proj_kernel() {
    extern __shared__ char sm[];
    char* sA_hi = sm;
    char* sA_lo = sm + 18432;
    char* sB_hi = sm + 36864;
    char* sB_lo = sm + 46080;

    const int tid = threadIdx.x;
    const int w = tid >> 5, lane = tid & 31, g = lane >> 2, tg = lane & 3;
    const int b = blockIdx.x >> 2, t = blockIdx.x & 3;
    const int h = blockIdx.y;
    const int which = blockIdx.z;
    const int l0 = t * 128;
    const int nrows = min(128, LSEQ - l0);
    const int m0 = b * LSEQ + l0;
    const int n0 = h * 64;
    const int mw = w * 16;

    const __nv_bfloat16* Xh = which ? g_v_hi : g_q_hi;
    const __nv_bfloat16* Xl = which ? g_v_lo : g_q_lo;
    const __nv_bfloat16* Wh = which ? g_wvsT_hi : g_wqsT_hi;
    const __nv_bfloat16* Wl = which ? g_wvsT_lo : g_wqsT_lo;

    float acc[8][4];
#pragma unroll
    for (int j = 0; j < 8; j++)
#pragma unroll
        for (int i = 0; i < 4; i++) acc[j][i] = 0.f;

    for (int kc = 0; kc < 4; kc++) {
        int k0 = kc * 64;
        __syncthreads();
        cp_tile(sA_hi, (const char*)(Xh + (size_t)m0 * FEAT + k0), 128, nrows, FEAT * 2, tid);
        cp_tile(sA_lo, (const char*)(Xl + (size_t)m0 * FEAT + k0), 128, nrows, FEAT * 2, tid);
        cp_tile(sB_hi, (const char*)(Wh + (size_t)n0 * FEAT + k0), 64, 64, FEAT * 2, tid);
        cp_tile(sB_lo, (const char*)(Wl + (size_t)n0 * FEAT + k0), 64, 64, FEAT * 2, tid);
        __syncthreads();
        mma_chunk<8>(acc, sA_hi, sA_lo, sB_hi, sB_lo, mw, g, tg);
    }

    const int bh = b * HEADS + h;
#pragma unroll
    for (int rr = 0; rr < 2; rr++) {
        int ml = mw + g + rr * 8;
        if (ml >= nrows) continue;
        int l = l0 + ml;
        if (which == 0) {
            size_t base = ((size_t)bh * LSEQ + l) * DK;
#pragma unroll
            for (int j = 0; j < 8; j++) {
                uint32_t hi, lo;
                split2(acc[j][rr * 2], acc[j][rr * 2 + 1], hi, lo);
                *(uint32_t*)(g_qh_hi + base + j * 8 + tg * 2) = hi;
                *(uint32_t*)(g_qh_lo + base + j * 8 + tg * 2) = lo;
            }
        } else {
#pragma unroll
            for (int j = 0; j < 8; j++) {
#pragma unroll
                for (int cc = 0; cc < 2; cc++) {
                    int d = j * 8 + tg * 2 + cc;
                    __nv_bfloat16 hh, ll;
                    split1(acc[j][rr * 2 + cc], hh, ll);
                    int idx = (bh * DK + d) * LPAD + l;
                    g_vT_hi[idx] = hh;
                    g_vT_lo[idx] = ll;
                }
            }
        }
    }
}

// ---------------------------------------------------------------------------
// synth: hid = relu(qh@w1+b1); logits = hid@w2+b2; softmax; out = P@vh
// grid (4, BH), block 256
// ---------------------------------------------------------------------------
#define SYN_SMEM (18432*2 + 18432*2 + 9216*2 + 256)

__global__ __launch_bounds__(256) void synth_kernel(const float* __restrict__ b1) {
    extern __shared__ char sm[];
    char* sP_hi = sm;                 // qh tile, later probs chunk
    char* sP_lo = sm + 18432;
    char* sH_hi = sm + 36864;         // hid
    char* sH_lo = sm + 55296;
    char* sB_hi = sm + 73728;
    char* sB_lo = sm + 82944;
    float* b1s  = (float*)(sm + 92160);

    const int tid = threadIdx.x;
    const int w = tid >> 5, lane = tid & 31, g = lane >> 2, tg = lane & 3;
    const int bh = blockIdx.y;
    const int r0 = blockIdx.x * 128;
    const int nrows = min(128, LSEQ - r0);
    const int mw = w * 16;

    cp_tile(sP_hi, (const char*)(g_qh_hi + ((size_t)bh * LSEQ + r0) * DK), 128, nrows, DK * 2, tid);
    cp_tile(sP_lo, (const char*)(g_qh_lo + ((size_t)bh * LSEQ + r0) * DK), 128, nrows, DK * 2, tid);
    cp_tile(sB_hi, (const char*)g_w1t_hi, 64, 64, DK * 2, tid);
    cp_tile(sB_lo, (const char*)g_w1t_lo, 64, 64, DK * 2, tid);
    if (tid < 64) b1s[tid] = b1[tid];
    __syncthreads();

    // phase 1
    {
        float accl[8][4];
#pragma unroll
        for (int j = 0; j < 8; j++)
#pragma unroll
            for (int i = 0; i < 4; i++) accl[j][i] = 0.f;
        mma_chunk<8>(accl, sP_hi, sP_lo, sB_hi, sB_lo, mw, g, tg);
        __syncthreads();
#pragma unroll
        for (int j = 0; j < 8; j++) {
            int col = j * 8 + tg * 2;
            uint32_t hi, lo;
            float x0 = fmaxf(accl[j][0] + b1s[col], 0.f);
            float x1 = fmaxf(accl[j][1] + b1s[col + 1], 0.f);
            split2(x0, x1, hi, lo);
            unsigned off = (unsigned)(((mw + g) * AST + col) * 2);
            *(uint32_t*)(sH_hi + off) = hi;
            *(uint32_t*)(sH_lo + off) = lo;
            x0 = fmaxf(accl[j][2] + b1s[col], 0.f);
            x1 = fmaxf(accl[j][3] + b1s[col + 1], 0.f);
            split2(x0, x1, hi, lo);
            off += 8 * AST * 2;
            *(uint32_t*)(sH_hi + off) = hi;
            *(uint32_t*)(sH_lo + off) = lo;
        }
    }
    __syncthreads();

    float acc_o[8][4];
#pragma unroll
    for (int j = 0; j < 8; j++)
#pragma unroll
        for (int i = 0; i < 4; i++) acc_o[j][i] = 0.f;
    float s0 = 0.f, s1 = 0.f;

    for (int c = 0; c < 8; c++) {
        int kc = c * 64;
        cp_tile(sB_hi, (const char*)(g_w2t_hi + kc * DK), 64, 64, DK * 2, tid);
        cp_tile(sB_lo, (const char*)(g_w2t_lo + kc * DK), 64, 64, DK * 2, tid);
        __syncthreads();
        float accl[8][4];
#pragma unroll
        for (int j = 0; j < 8; j++)
#pragma unroll
            for (int i = 0; i < 4; i++) accl[j][i] = 0.f;
        mma_chunk<8>(accl, sH_hi, sH_lo, sB_hi, sB_lo, mw, g, tg);
        __syncthreads();
        // softmax partial + probs into sP
#pragma unroll
        for (int j = 0; j < 8; j++) {
            int col = kc + j * 8 + tg * 2;
            float bb0 = __ldg(&g_b2p[col]), bb1 = __ldg(&g_b2p[col + 1]);
            float p0 = __expf(fminf(accl[j][0] + bb0, 80.f));
            float p1 = __expf(fminf(accl[j][1] + bb1, 80.f));
            s0 += p0 + p1;
            uint32_t hi, lo;
            split2(p0, p1, hi, lo);
            unsigned off = (unsigned)(((mw + g) * AST + j * 8 + tg * 2) * 2);
            *(uint32_t*)(sP_hi + off) = hi;
            *(uint32_t*)(sP_lo + off) = lo;
            p0 = __expf(fminf(accl[j][2] + bb0, 80.f));
            p1 = __expf(fminf(accl[j][3] + bb1, 80.f));
            s1 += p0 + p1;
            split2(p0, p1, hi, lo);
            off += 8 * AST * 2;
            *(uint32_t*)(sP_hi + off) = hi;
            *(uint32_t*)(sP_lo + off) = lo;
        }
        cp_tile(sB_hi, (const char*)(g_vT_hi + (size_t)bh * DK * LPAD + kc), 64, 64, LPAD * 2, tid);
        cp_tile(sB_lo, (const char*)(g_vT_lo + (size_t)bh * DK * LPAD + kc), 64, 64, LPAD * 2, tid);
        __syncthreads();
        mma_chunk<8>(acc_o, sP_hi, sP_lo, sB_hi, sB_lo, mw, g, tg);
        __syncthreads();
    }

    s0 += __shfl_xor_sync(0xffffffffu, s0, 1);
    s0 += __shfl_xor_sync(0xffffffffu, s0, 2);
    s1 += __shfl_xor_sync(0xffffffffu, s1, 1);
    s1 += __shfl_xor_sync(0xffffffffu, s1, 2);
    const float inv0 = 1.f / s0, inv1 = 1.f / s1;
    const int b = bh >> 2, hh = bh & 3;
#pragma unroll
    for (int rr = 0; rr < 2; rr++) {
        int ml = mw + g + rr * 8;
        if (ml >= nrows) continue;
        float invv = rr ? inv1 : inv0;
        size_t base = ((size_t)(b * LSEQ + r0 + ml)) * FEAT + hh * 64;
#pragma unroll
        for (int j = 0; j < 8; j++) {
            uint32_t hi, lo;
            split2(acc_o[j][rr * 2] * invv, acc_o[j][rr * 2 + 1] * invv, hi, lo);
            *(uint32_t*)(g_pre_hi + base + j * 8 + tg * 2) = hi;
            *(uint32_t*)(g_pre_lo + base + j * 8 + tg * 2) = lo;
        }
    }
}

// ---------------------------------------------------------------------------
// fc + residual + LayerNorm. grid 250, block 256; warp tile 16 x 256.
// ---------------------------------------------------------------------------
#define FC_SMEM (18432*2 + 36864*2)

__global__ __launch_bounds__(256) void fc_ln_kernel(const float* __restrict__ q,
                                                    const float* __restrict__ lng,
                                                    const float* __restrict__ lnb,
                                                    float* __restrict__ out) {
    extern __shared__ char sm[];
    char* sA_hi = sm;
    char* sA_lo = sm + 18432;
    char* sB_hi = sm + 36864;       // 256 rows
    char* sB_lo = sm + 73728;

    const int tid = threadIdx.x;
    const int w = tid >> 5, lane = tid & 31, g = lane >> 2, tg = lane & 3;
    const int m0 = blockIdx.x * 128;
    const int mw = w * 16;

    float acc[32][4];
#pragma unroll
    for (int j = 0; j < 32; j++)
#pragma unroll
        for (int i = 0; i < 4; i++) acc[j][i] = 0.f;

    for (int kc = 0; kc < 4; kc++) {
        int k0 = kc * 64;
        __syncthreads();
        cp_tile(sA_hi, (const char*)(g_pre_hi + (size_t)m0 * FEAT + k0), 128, 128, FEAT * 2, tid);
        cp_tile(sA_lo, (const char*)(g_pre_lo + (size_t)m0 * FEAT + k0), 128, 128, FEAT * 2, tid);
        cp_tile(sB_hi, (const char*)(g_fcwT_hi + k0), 256, 256, FEAT * 2, tid);
        cp_tile(sB_lo, (const char*)(g_fcwT_lo + k0), 256, 256, FEAT * 2, tid);
        __syncthreads();
        mma_chunk<32>(acc, sA_hi, sA_lo, sB_hi, sB_lo, mw, g, tg);
    }

#pragma unroll
    for (int rr = 0; rr < 2; rr++) {
        int r = mw + g + rr * 8;
        const float* qrow = q + (size_t)(m0 + r) * FEAT;
        float s = 0.f, s2 = 0.f;
#pragma unroll
        for (int j = 0; j < 32; j++) {
            float2 qq = *(const float2*)(qrow + j * 8 + tg * 2);
            float x0 = acc[j][rr * 2]     + qq.x;
            float x1 = acc[j][rr * 2 + 1] + qq.y;
            acc[j][rr * 2] = x0;
            acc[j][rr * 2 + 1] = x1;
            s += x0 + x1;
            s2 += x0 * x0 + x1 * x1;
        }
        s  += __shfl_xor_sync(0xffffffffu, s, 1);
        s  += __shfl_xor_sync(0xffffffffu, s, 2);
        s2 += __shfl_xor_sync(0xffffffffu, s2, 1);
        s2 += __shfl_xor_sync(0xffffffffu, s2, 2);
        float mu = s * (1.f / FEAT);
        float rstd = rsqrtf(s2 * (1.f / FEAT) - mu * mu + 1e-6f);
        float* orow = out + (size_t)(m0 + r) * FEAT;
#pragma unroll
        for (int j = 0; j < 32; j++) {
            int col = j * 8 + tg * 2;
            float g0 = __ldg(&lng[col]), g1 = __ldg(&lng[col + 1]);
            float bb0 = __ldg(&lnb[col]), bb1 = __ldg(&lnb[col + 1]);
            float2 o;
            o.x = (acc[j][rr * 2]     - mu) * rstd * g0 + bb0;
            o.y = (acc[j][rr * 2 + 1] - mu) * rstd * g1 + bb1;
            *(float2*)(orow + col) = o;
        }
    }
}

// ---------------------------------------------------------------------------
extern "C" void kernel_launch(void* const* d_in, const int* in_sizes, int n_in,
                              void* d_out, int out_size)
{
    (void)in_sizes; (void)n_in; (void)out_size;
    const float* q    = (const float*)d_in[0];
    const float* v    = (const float*)d_in[2];
    const float* w_qs = (const float*)d_in[3];
    const float* w_vs = (const float*)d_in[4];
    const float* w1   = (const float*)d_in[5];
    const float* b1   = (const float*)d_in[6];
    const float* w2   = (const float*)d_in[7];
    const float* b2   = (const float*)d_in[8];
    const float* fcw  = (const float*)d_in[9];
    const float* lng  = (const float*)d_in[10];
    const float* lnb  = (const float*)d_in[11];
    float* out = (float*)d_out;

    cudaFuncSetAttribute(proj_kernel,  cudaFuncAttributeMaxDynamicSharedMemorySize, PROJ_SMEM);
    cudaFuncSetAttribute(synth_kernel, cudaFuncAttributeMaxDynamicSharedMemorySize, SYN_SMEM);
    cudaFuncSetAttribute(fc_ln_kernel, cudaFuncAttributeMaxDynamicSharedMemorySize, FC_SMEM);

    setup_w<<<128, 256>>>(w_qs, w_vs, fcw, w1, w2, b2);
    convert_kernel<<<2048, 256>>>(q, v);
    proj_kernel<<<dim3(BATCH * 4, HEADS, 2), 256, PROJ_SMEM>>>();
    synth_kernel<<<dim3(4, BH), 256, SYN_SMEM>>>(b1);
    fc_ln_kernel<<<250, 256, FC_SMEM>>>(q, lng, lnb, out);
}

// round 7
// speedup vs baseline: 3.2856x; 1.0292x over previous
#include <cuda_runtime.h>
#include <cuda_bf16.h>
#include <cstdint>

#define BATCH 64
#define LSEQ  500
#define FEAT  256
#define HEADS 4
#define DK    64
#define BH    (BATCH*HEADS)       // 256
#define MROWS (BATCH*LSEQ)        // 32000
#define LPAD  512
#define AST   72                  // smem row stride (bf16 elems) -> 144B

// ---------------- device scratch ----------------
static __device__ __nv_bfloat16 g_wqsT_hi[FEAT*FEAT], g_wqsT_lo[FEAT*FEAT];
static __device__ __nv_bfloat16 g_wvsT_hi[FEAT*FEAT], g_wvsT_lo[FEAT*FEAT];
static __device__ __nv_bfloat16 g_fcwT_hi[FEAT*FEAT], g_fcwT_lo[FEAT*FEAT];
static __device__ __nv_bfloat16 g_w1t_hi[DK*DK],      g_w1t_lo[DK*DK];
static __device__ __nv_bfloat16 g_w2t_hi[LPAD*DK],    g_w2t_lo[LPAD*DK];
static __device__ float         g_b2p[LPAD];
static __device__ __nv_bfloat16 g_qh_hi[BH*LSEQ*DK + 1024], g_qh_lo[BH*LSEQ*DK + 1024]; // pad: tile-3 overread
static __device__ __nv_bfloat16 g_vT_hi[BH*DK*LPAD],  g_vT_lo[BH*DK*LPAD];   // [bh][d][l] pad 0
static __device__ __nv_bfloat16 g_pre_hi[MROWS*FEAT], g_pre_lo[MROWS*FEAT];

// ---------------- helpers ----------------
__device__ __forceinline__ uint32_t smem_u32(const void* p) {
    uint32_t a;
    asm("{ .reg .u64 t; cvta.to.shared.u64 t, %1; cvt.u32.u64 %0, t; }" : "=r"(a) : "l"(p));
    return a;
}
__device__ __forceinline__ uint32_t pack2(__nv_bfloat16 a, __nv_bfloat16 b) {
    return (uint32_t)__bfloat16_as_ushort(a) | ((uint32_t)__bfloat16_as_ushort(b) << 16);
}
__device__ __forceinline__ void split1(float x, __nv_bfloat16& h, __nv_bfloat16& l) {
    h = __float2bfloat16(x);
    l = __float2bfloat16(x - __bfloat162float(h));
}
__device__ __forceinline__ void split2(float x0, float x1, uint32_t& hi, uint32_t& lo) {
    __nv_bfloat16 h0, l0, h1, l1;
    split1(x0, h0, l0);
    split1(x1, h1, l1);
    hi = pack2(h0, h1);
    lo = pack2(l0, l1);
}

__device__ __forceinline__ void mma_bf16(float acc[4], uint32_t a0, uint32_t a1,
                                         uint32_t a2, uint32_t a3,
                                         uint32_t b0, uint32_t b1) {
    asm volatile(
        "mma.sync.aligned.m16n8k16.row.col.f32.bf16.bf16.f32 "
        "{%0,%1,%2,%3}, {%4,%5,%6,%7}, {%8,%9}, {%0,%1,%2,%3};"
        : "+f"(acc[0]), "+f"(acc[1]), "+f"(acc[2]), "+f"(acc[3])
        : "r"(a0), "r"(a1), "r"(a2), "r"(a3), "r"(b0), "r"(b1));
}

template <int NF>
__device__ __forceinline__ void mma_chunk(float (*acc)[4],
                                          const char* aH, const char* aL,
                                          const char* bH, const char* bL,
                                          int mw, int g, int tg) {
#pragma unroll
    for (int ks = 0; ks < 4; ks++) {
        unsigned a0off = (unsigned)(((mw + g) * AST + ks * 16 + tg * 2) * 2);
        unsigned a1off = a0off + 8 * AST * 2;
        uint32_t ah0 = *(const uint32_t*)(aH + a0off);
        uint32_t ah1 = *(const uint32_t*)(aH + a1off);
        uint32_t ah2 = *(const uint32_t*)(aH + a0off + 16);
        uint32_t ah3 = *(const uint32_t*)(aH + a1off + 16);
        uint32_t al0 = *(const uint32_t*)(aL + a0off);
        uint32_t al1 = *(const uint32_t*)(aL + a1off);
        uint32_t al2 = *(const uint32_t*)(aL + a0off + 16);
        uint32_t al3 = *(const uint32_t*)(aL + a1off + 16);
#pragma unroll
        for (int j = 0; j < NF; j++) {
            unsigned boff = (unsigned)(((j * 8 + g) * AST + ks * 16 + tg * 2) * 2);
            uint32_t bh0 = *(const uint32_t*)(bH + boff);
            uint32_t bh1 = *(const uint32_t*)(bH + boff + 16);
            uint32_t bl0 = *(const uint32_t*)(bL + boff);
            uint32_t bl1 = *(const uint32_t*)(bL + boff + 16);
            mma_bf16(acc[j], ah0, ah1, ah2, ah3, bh0, bh1);
            mma_bf16(acc[j], ah0, ah1, ah2, ah3, bl0, bl1);
            mma_bf16(acc[j], al0, al1, al2, al3, bh0, bh1);
        }
    }
}

// sync copy: rows x 128B gmem -> stride-144B smem, zero-fill invalid rows
__device__ __forceinline__ void cp_tile(char* dst, const char* src, int rows,
                                        int valid, int gstride, int tid) {
    for (int i = tid; i < rows * 8; i += 256) {
        int r = i >> 3, c = (i & 7) << 4;
        uint4 v = make_uint4(0u, 0u, 0u, 0u);
        if (r < valid) v = *(const uint4*)(src + (size_t)r * gstride + c);
        *(uint4*)(dst + r * (AST * 2) + c) = v;
    }
}

// async copy (no bounds): rows8 = rows*8 chunks of 16B
__device__ __forceinline__ void cpa16(uint32_t dst, const void* src) {
    asm volatile("cp.async.ca.shared.global [%0], [%1], 16;" :: "r"(dst), "l"(src));
}
#define CP_COMMIT() asm volatile("cp.async.commit_group;" ::: "memory")
#define CP_WAIT(n)  asm volatile("cp.async.wait_group %0;" :: "n"(n) : "memory")

__device__ __forceinline__ void cp_tile_async(uint32_t dst, const char* src,
                                              int rows8, int gstride, int tid) {
    for (int i = tid; i < rows8; i += 256) {
        int r = i >> 3, c = (i & 7) << 4;
        cpa16(dst + (unsigned)(r * (AST * 2) + c), src + (size_t)r * gstride + c);
    }
}

// ---------------------------------------------------------------------------
// setup: transpose + split weights
// ---------------------------------------------------------------------------
__global__ __launch_bounds__(256) void setup_w(const float* __restrict__ w_qs,
                                               const float* __restrict__ w_vs,
                                               const float* __restrict__ fcw,
                                               const float* __restrict__ w1,
                                               const float* __restrict__ w2,
                                               const float* __restrict__ b2) {
    int i0 = blockIdx.x * blockDim.x + threadIdx.x;
    int nt = gridDim.x * blockDim.x;
    for (int t = i0; t < FEAT * FEAT; t += nt) {
        int n = t >> 8, k = t & 255;
        split1(w_qs[k * FEAT + n], g_wqsT_hi[t], g_wqsT_lo[t]);
        split1(w_vs[k * FEAT + n], g_wvsT_hi[t], g_wvsT_lo[t]);
        split1(fcw [k * FEAT + n], g_fcwT_hi[t], g_fcwT_lo[t]);
    }
    for (int t = i0; t < DK * DK; t += nt) {
        int n = t >> 6, k = t & 63;
        split1(w1[k * DK + n], g_w1t_hi[t], g_w1t_lo[t]);
    }
    for (int t = i0; t < LPAD * DK; t += nt) {
        int n = t >> 6, k = t & 63;
        float f = (n < LSEQ) ? w2[k * LSEQ + n] : 0.f;
        split1(f, g_w2t_hi[t], g_w2t_lo[t]);
    }
    for (int t = i0; t < LPAD; t += nt)
        g_b2p[t] = (t < LSEQ) ? b2[t] : -1e30f;
}

// ---------------------------------------------------------------------------
// proj: fp32 X @ W -> qh / vT ; conversion fused (loads fp32, splits in-reg)
// grid (BATCH*4, HEADS, 2), block 256
// ---------------------------------------------------------------------------
#define PROJ_SMEM (18432*2 + 9216*2)

__global__ __launch_bounds__(256) void proj_kernel(const float* __restrict__ q,
                                                   const float* __restrict__ v) {
    extern __shared__ char sm[];
    char* sA_hi = sm;
    char* sA_lo = sm + 18432;
    char* sB_hi = sm + 36864;
    char* sB_lo = sm + 46080;

    const int tid = threadIdx.x;
    const int w = tid >> 5, lane = tid & 31, g = lane >> 2, tg = lane & 3;
    const int b = blockIdx.x >> 2, t = blockIdx.x & 3;
    const int h = blockIdx.y;
    const int which = blockIdx.z;
    const int l0 = t * 128;
    const int nrows = min(128, LSEQ - l0);
    const int m0 = b * LSEQ + l0;
    const int n0 = h * 64;
    const int mw = w * 16;

    const float* X = which ? v : q;
    const __nv_bfloat16* Wh = which ? g_wvsT_hi : g_wqsT_hi;
    const __nv_bfloat16* Wl = which ? g_wvsT_lo : g_wqsT_lo;

    float acc[8][4];
#pragma unroll
    for (int j = 0; j < 8; j++)
#pragma unroll
        for (int i = 0; i < 4; i++) acc[j][i] = 0.f;

    for (int kc = 0; kc < 4; kc++) {
        int k0 = kc * 64;
        __syncthreads();
        // A: fp32 load + split -> smem (128 rows x 64 cols)
        for (int i = tid; i < 128 * 16; i += 256) {
            int r = i >> 4, c4 = (i & 15) << 2;
            float4 a = make_float4(0.f, 0.f, 0.f, 0.f);
            if (r < nrows) a = *(const float4*)(X + (size_t)(m0 + r) * FEAT + k0 + c4);
            uint32_t h0, L0, h1, L1;
            split2(a.x, a.y, h0, L0);
            split2(a.z, a.w, h1, L1);
            unsigned off = (unsigned)(r * (AST * 2) + c4 * 2);
            *(uint2*)(sA_hi + off) = make_uint2(h0, h1);
            *(uint2*)(sA_lo + off) = make_uint2(L0, L1);
        }
        cp_tile(sB_hi, (const char*)(Wh + (size_t)n0 * FEAT + k0), 64, 64, FEAT * 2, tid);
        cp_tile(sB_lo, (const char*)(Wl + (size_t)n0 * FEAT + k0), 64, 64, FEAT * 2, tid);
        __syncthreads();
        mma_chunk<8>(acc, sA_hi, sA_lo, sB_hi, sB_lo, mw, g, tg);
    }

    const int bh = b * HEADS + h;
#pragma unroll
    for (int rr = 0; rr < 2; rr++) {
        int ml = mw + g + rr * 8;
        if (ml >= nrows) continue;
        int l = l0 + ml;
        if (which == 0) {
            size_t base = ((size_t)bh * LSEQ + l) * DK;
#pragma unroll
            for (int j = 0; j < 8; j++) {
                uint32_t hi, lo;
                split2(acc[j][rr * 2], acc[j][rr * 2 + 1], hi, lo);
                *(uint32_t*)(g_qh_hi + base + j * 8 + tg * 2) = hi;
                *(uint32_t*)(g_qh_lo + base + j * 8 + tg * 2) = lo;
            }
        } else {
#pragma unroll
            for (int j = 0; j < 8; j++) {
#pragma unroll
                for (int cc = 0; cc < 2; cc++) {
                    int d = j * 8 + tg * 2 + cc;
                    __nv_bfloat16 hh, ll;
                    split1(acc[j][rr * 2 + cc], hh, ll);
                    int idx = (bh * DK + d) * LPAD + l;
                    g_vT_hi[idx] = hh;
                    g_vT_lo[idx] = ll;
                }
            }
        }
    }
}

// ---------------------------------------------------------------------------
// synth: cp.async depth-3 pipelined. grid (4, BH), block 256.
// smem layout (bytes):
//   A (qh/probs) hi/lo : 0      / 18432
//   H (hid)      hi/lo : 36864  / 55296
//   W1           hi/lo : 73728  / 82944
//   W ring x3 (hi,lo pair 18432 each): 92160 + i*18432
//   V ring x3:                         147456 + i*18432
//   b1s: 202752
// ---------------------------------------------------------------------------
#define OFF_A   0
#define OFF_H   36864
#define OFF_W1  73728
#define OFF_W   92160
#define OFF_V   147456
#define OFF_B1  202752
#define SYN_SMEM (202752 + 256)

__global__ __launch_bounds__(256) void synth_kernel(const float* __restrict__ b1) {
    extern __shared__ char sm[];
    const uint32_t sb = smem_u32(sm);
    float* b1s = (float*)(sm + OFF_B1);

    const int tid = threadIdx.x;
    const int w = tid >> 5, lane = tid & 31, g = lane >> 2, tg = lane & 3;
    const int bh = blockIdx.y;
    const int r0 = blockIdx.x * 128;
    const int nrows = min(128, LSEQ - r0);
    const int mw = w * 16;

    const size_t qh_base = ((size_t)bh * LSEQ + r0) * DK;
    const size_t vt_base = (size_t)bh * DK * LPAD;

    // G_init: qh tile + w1
    cp_tile_async(sb + OFF_A,          (const char*)(g_qh_hi + qh_base), 1024, DK * 2, tid);
    cp_tile_async(sb + OFF_A + 18432,  (const char*)(g_qh_lo + qh_base), 1024, DK * 2, tid);
    cp_tile_async(sb + OFF_W1,         (const char*)g_w1t_hi, 512, DK * 2, tid);
    cp_tile_async(sb + OFF_W1 + 9216,  (const char*)g_w1t_lo, 512, DK * 2, tid);
    CP_COMMIT();
    // G0, G1: chunks 0 and 1 (w2 + vT)
#pragma unroll
    for (int c = 0; c < 2; c++) {
        uint32_t wb = sb + OFF_W + c * 18432;
        uint32_t vb = sb + OFF_V + c * 18432;
        cp_tile_async(wb,        (const char*)(g_w2t_hi + c * 64 * DK), 512, DK * 2, tid);
        cp_tile_async(wb + 9216, (const char*)(g_w2t_lo + c * 64 * DK), 512, DK * 2, tid);
        cp_tile_async(vb,        (const char*)(g_vT_hi + vt_base + c * 64), 512, LPAD * 2, tid);
        cp_tile_async(vb + 9216, (const char*)(g_vT_lo + vt_base + c * 64), 512, LPAD * 2, tid);
        CP_COMMIT();
    }
    if (tid < 64) b1s[tid] = b1[tid];
    CP_WAIT(2);           // qh + w1 ready
    __syncthreads();

    // phase 1: hid = relu(qh@w1 + b1) -> sH (same-warp rows, syncwarp only)
    {
        float accl[8][4];
#pragma unroll
        for (int j = 0; j < 8; j++)
#pragma unroll
            for (int i = 0; i < 4; i++) accl[j][i] = 0.f;
        mma_chunk<8>(accl, sm + OFF_A, sm + OFF_A + 18432,
                     sm + OFF_W1, sm + OFF_W1 + 9216, mw, g, tg);
#pragma unroll
        for (int j = 0; j < 8; j++) {
            int col = j * 8 + tg * 2;
            uint32_t hi, lo;
            float x0 = fmaxf(accl[j][0] + b1s[col], 0.f);
            float x1 = fmaxf(accl[j][1] + b1s[col + 1], 0.f);
            split2(x0, x1, hi, lo);
            unsigned off = (unsigned)(((mw + g) * AST + col) * 2);
            *(uint32_t*)(sm + OFF_H + off) = hi;
            *(uint32_t*)(sm + OFF_H + 18432 + off) = lo;
            x0 = fmaxf(accl[j][2] + b1s[col], 0.f);
            x1 = fmaxf(accl[j][3] + b1s[col + 1], 0.f);
            split2(x0, x1, hi, lo);
            off += 8 * AST * 2;
            *(uint32_t*)(sm + OFF_H + off) = hi;
            *(uint32_t*)(sm + OFF_H + 18432 + off) = lo;
        }
        __syncwarp();
    }

    float acc_o[8][4];
#pragma unroll
    for (int j = 0; j < 8; j++)
#pragma unroll
        for (int i = 0; i < 4; i++) acc_o[j][i] = 0.f;
    float s0 = 0.f, s1 = 0.f;

    for (int c = 0; c < 8; c++) {
        CP_WAIT(1);       // chunk c resident; chunk c+1 may be in flight
        __syncthreads();  // one block barrier per chunk

        // prefetch chunk c+2 into ring slot (c+2)%3 (freed by chunk c-1)
        if (c + 2 < 8) {
            int cn = c + 2, slot = cn % 3;
            uint32_t wb = sb + OFF_W + slot * 18432;
            uint32_t vb = sb + OFF_V + slot * 18432;
            cp_tile_async(wb,        (const char*)(g_w2t_hi + cn * 64 * DK), 512, DK * 2, tid);
            cp_tile_async(wb + 9216, (const char*)(g_w2t_lo + cn * 64 * DK), 512, DK * 2, tid);
            cp_tile_async(vb,        (const char*)(g_vT_hi + vt_base + cn * 64), 512, LPAD * 2, tid);
            cp_tile_async(vb + 9216, (const char*)(g_vT_lo + vt_base + cn * 64), 512, LPAD * 2, tid);
        }
        CP_COMMIT();      // keep group count uniform (empty group when no prefetch)

        const char* wb = sm + OFF_W + (c % 3) * 18432;
        const char* vb = sm + OFF_V + (c % 3) * 18432;

        // logits chunk = hid @ w2[c]
        float accl[8][4];
#pragma unroll
        for (int j = 0; j < 8; j++)
#pragma unroll
            for (int i = 0; i < 4; i++) accl[j][i] = 0.f;
        mma_chunk<8>(accl, sm + OFF_H, sm + OFF_H + 18432, wb, wb + 9216, mw, g, tg);

        // probs = exp(logit + b2) -> sA (same-warp rows)
        const int kc = c * 64;
#pragma unroll
        for (int j = 0; j < 8; j++) {
            int col = kc + j * 8 + tg * 2;
            float bb0 = __ldg(&g_b2p[col]), bb1 = __ldg(&g_b2p[col + 1]);
            float p0 = __expf(fminf(accl[j][0] + bb0, 80.f));
            float p1 = __expf(fminf(accl[j][1] + bb1, 80.f));
            s0 += p0 + p1;
            uint32_t hi, lo;
            split2(p0, p1, hi, lo);
            unsigned off = (unsigned)(((mw + g) * AST + j * 8 + tg * 2) * 2);
            *(uint32_t*)(sm + OFF_A + off) = hi;
            *(uint32_t*)(sm + OFF_A + 18432 + off) = lo;
            p0 = __expf(fminf(accl[j][2] + bb0, 80.f));
            p1 = __expf(fminf(accl[j][3] + bb1, 80.f));
            s1 += p0 + p1;
            split2(p0, p1, hi, lo);
            off += 8 * AST * 2;
            *(uint32_t*)(sm + OFF_A + off) = hi;
            *(uint32_t*)(sm + OFF_A + 18432 + off) = lo;
        }
        __syncwarp();

        // out += P @ vT[c]
        mma_chunk<8>(acc_o, sm + OFF_A, sm + OFF_A + 18432, vb, vb + 9216, mw, g, tg);
    }

    s0 += __shfl_xor_sync(0xffffffffu, s0, 1);
    s0 += __shfl_xor_sync(0xffffffffu, s0, 2);
    s1 += __shfl_xor_sync(0xffffffffu, s1, 1);
    s1 += __shfl_xor_sync(0xffffffffu, s1, 2);
    const float inv0 = 1.f / s0, inv1 = 1.f / s1;
    const int b = bh >> 2, hh = bh & 3;
#pragma unroll
    for (int rr = 0; rr < 2; rr++) {
        int ml = mw + g + rr * 8;
        if (ml >= nrows) continue;
        float invv = rr ? inv1 : inv0;
        size_t base = ((size_t)(b * LSEQ + r0 + ml)) * FEAT + hh * 64;
#pragma unroll
        for (int j = 0; j < 8; j++) {
            uint32_t hi, lo;
            split2(acc_o[j][rr * 2] * invv, acc_o[j][rr * 2 + 1] * invv, hi, lo);
            *(uint32_t*)(g_pre_hi + base + j * 8 + tg * 2) = hi;
            *(uint32_t*)(g_pre_lo + base + j * 8 + tg * 2) = lo;
        }
    }
}

// ---------------------------------------------------------------------------
// fc + residual + LayerNorm. grid 250, block 256; warp tile 16 x 256.
// ---------------------------------------------------------------------------
#define FC_SMEM (18432*2 + 36864*2)

__global__ __launch_bounds__(256) void fc_ln_kernel(const float* __restrict__ q,
                                                    const float* __restrict__ lng,
                                                    const float* __restrict__ lnb,
                                                    float* __restrict__ out) {
    extern __shared__ char sm[];
    char* sA_hi = sm;
    char* sA_lo = sm + 18432;
    char* sB_hi = sm + 36864;
    char* sB_lo = sm + 73728;

    const int tid = threadIdx.x;
    const int w = tid >> 5, lane = tid & 31, g = lane >> 2, tg = lane & 3;
    const int m0 = blockIdx.x * 128;
    const int mw = w * 16;

    float acc[32][4];
#pragma unroll
    for (int j = 0; j < 32; j++)
#pragma unroll
        for (int i = 0; i < 4; i++) acc[j][i] = 0.f;

    for (int kc = 0; kc < 4; kc++) {
        int k0 = kc * 64;
        __syncthreads();
        cp_tile(sA_hi, (const char*)(g_pre_hi + (size_t)m0 * FEAT + k0), 128, 128, FEAT * 2, tid);
        cp_tile(sA_lo, (const char*)(g_pre_lo + (size_t)m0 * FEAT + k0), 128, 128, FEAT * 2, tid);
        cp_tile(sB_hi, (const char*)(g_fcwT_hi + k0), 256, 256, FEAT * 2, tid);
        cp_tile(sB_lo, (const char*)(g_fcwT_lo + k0), 256, 256, FEAT * 2, tid);
        __syncthreads();
        mma_chunk<32>(acc, sA_hi, sA_lo, sB_hi, sB_lo, mw, g, tg);
    }

#pragma unroll
    for (int rr = 0; rr < 2; rr++) {
        int r = mw + g + rr * 8;
        const float* qrow = q + (size_t)(m0 + r) * FEAT;
        float s = 0.f, s2 = 0.f;
#pragma unroll
        for (int j = 0; j < 32; j++) {
            float2 qq = *(const float2*)(qrow + j * 8 + tg * 2);
            float x0 = acc[j][rr * 2]     + qq.x;
            float x1 = acc[j][rr * 2 + 1] + qq.y;
            acc[j][rr * 2] = x0;
            acc[j][rr * 2 + 1] = x1;
            s += x0 + x1;
            s2 += x0 * x0 + x1 * x1;
        }
        s  += __shfl_xor_sync(0xffffffffu, s, 1);
        s  += __shfl_xor_sync(0xffffffffu, s, 2);
        s2 += __shfl_xor_sync(0xffffffffu, s2, 1);
        s2 += __shfl_xor_sync(0xffffffffu, s2, 2);
        float mu = s * (1.f / FEAT);
        float rstd = rsqrtf(s2 * (1.f / FEAT) - mu * mu + 1e-6f);
        float* orow = out + (size_t)(m0 + r) * FEAT;
#pragma unroll
        for (int j = 0; j < 32; j++) {
            int col = j * 8 + tg * 2;
            float g0 = __ldg(&lng[col]), g1 = __ldg(&lng[col + 1]);
            float bb0 = __ldg(&lnb[col]), bb1 = __ldg(&lnb[col + 1]);
            float2 o;
            o.x = (acc[j][rr * 2]     - mu) * rstd * g0 + bb0;
            o.y = (acc[j][rr * 2 + 1] - mu) * rstd * g1 + bb1;
            *(float2*)(orow + col) = o;
        }
    }
}

// ---------------------------------------------------------------------------
extern "C" void kernel_launch(void* const* d_in, const int* in_sizes, int n_in,
                              void* d_out, int out_size)
{
    (void)in_sizes; (void)n_in; (void)out_size;
    const float* q    = (const float*)d_in[0];
    const float* v    = (const float*)d_in[2];
    const float* w_qs = (const float*)d_in[3];
    const float* w_vs = (const float*)d_in[4];
    const float* w1   = (const float*)d_in[5];
    const float* b1   = (const float*)d_in[6];
    const float* w2   = (const float*)d_in[7];
    const float* b2   = (const float*)d_in[8];
    const float* fcw  = (const float*)d_in[9];
    const float* lng  = (const float*)d_in[10];
    const float* lnb  = (const float*)d_in[11];
    float* out = (float*)d_out;

    cudaFuncSetAttribute(proj_kernel,  cudaFuncAttributeMaxDynamicSharedMemorySize, PROJ_SMEM);
    cudaFuncSetAttribute(synth_kernel, cudaFuncAttributeMaxDynamicSharedMemorySize, SYN_SMEM);
    cudaFuncSetAttribute(fc_ln_kernel, cudaFuncAttributeMaxDynamicSharedMemorySize, FC_SMEM);

    setup_w<<<128, 256>>>(w_qs, w_vs, fcw, w1, w2, b2);
    proj_kernel<<<dim3(BATCH * 4, HEADS, 2), 256, PROJ_SMEM>>>(q, v);
    synth_kernel<<<dim3(4, BH), 256, SYN_SMEM>>>(b1);
    fc_ln_kernel<<<250, 256, FC_SMEM>>>(q, lng, lnb, out);
}